// round 15
// baseline (speedup 1.0000x reference)
#include <cuda_runtime.h>
#include <cuda_bf16.h>
#include <cstdint>

#define GG   128
#define AA   100
#define WIN  10
#define FDIM 16
#define HD   128
#define K1   (WIN*FDIM)   // 160
#define NN   (GG*AA)
#define MM   112          // padded M (100 -> 112)

typedef unsigned long long ull;

// ===== f32x2 helpers (conv kernel) =====
__device__ __forceinline__ ull pk2(float lo, float hi) {
    ull r; asm("mov.b64 %0, {%1,%2};" : "=l"(r) : "f"(lo), "f"(hi)); return r;
}
__device__ __forceinline__ ull fma2(ull a, ull b, ull c) {
    ull d; asm("fma.rn.f32x2 %0, %1, %2, %3;" : "=l"(d) : "l"(a), "l"(b), "l"(c)); return d;
}
__device__ __forceinline__ ull add2(ull a, ull b) {
    ull d; asm("add.rn.f32x2 %0, %1, %2;" : "=l"(d) : "l"(a), "l"(b)); return d;
}
__device__ __forceinline__ float2 upk2(ull v) {
    float lo, hi; asm("mov.b64 {%0,%1}, %2;" : "=f"(lo), "=f"(hi) : "l"(v));
    return make_float2(lo, hi);
}

// ===== mma/ldmatrix/stmatrix helpers =====
__device__ __forceinline__ uint32_t smem_u32(const void* p) {
    uint32_t a; asm("{ .reg .u64 t; cvta.to.shared.u64 t, %1; cvt.u32.u64 %0, t; }"
                    : "=r"(a) : "l"(p)); return a;
}
__device__ __forceinline__ void ldsm4(uint32_t addr, uint32_t r[4]) {
    asm volatile("ldmatrix.sync.aligned.m8n8.x4.shared.b16 {%0,%1,%2,%3}, [%4];"
        : "=r"(r[0]), "=r"(r[1]), "=r"(r[2]), "=r"(r[3]) : "r"(addr));
}
__device__ __forceinline__ void stsm4t(uint32_t addr, uint32_t x0, uint32_t x1,
                                       uint32_t x2, uint32_t x3) {
    asm volatile("stmatrix.sync.aligned.m8n8.x4.trans.shared.b16 [%0], {%1,%2,%3,%4};"
        :: "r"(addr), "r"(x0), "r"(x1), "r"(x2), "r"(x3) : "memory");
}
__device__ __forceinline__ void stsm4(uint32_t addr, uint32_t x0, uint32_t x1,
                                      uint32_t x2, uint32_t x3) {
    asm volatile("stmatrix.sync.aligned.m8n8.x4.shared.b16 [%0], {%1,%2,%3,%4};"
        :: "r"(addr), "r"(x0), "r"(x1), "r"(x2), "r"(x3) : "memory");
}
__device__ __forceinline__ void mma16816(float* c, const uint32_t a[4],
                                         uint32_t b0, uint32_t b1) {
    asm volatile("mma.sync.aligned.m16n8k16.row.col.f32.bf16.bf16.f32 "
        "{%0,%1,%2,%3}, {%4,%5,%6,%7}, {%8,%9}, {%0,%1,%2,%3};"
        : "+f"(c[0]), "+f"(c[1]), "+f"(c[2]), "+f"(c[3])
        : "r"(a[0]), "r"(a[1]), "r"(a[2]), "r"(a[3]), "r"(b0), "r"(b1));
}
__device__ __forceinline__ void splitf(float v, float& vh, float& vl) {
    vh = __bfloat162float(__float2bfloat16(v)); vl = v - vh;
}
__device__ __forceinline__ void st_bf(char* base, uint32_t off, float v) {
    *reinterpret_cast<__nv_bfloat16*>(base + off) = __float2bfloat16(v);
}
__device__ __forceinline__ uint32_t pkbf(float a, float b) {
    __nv_bfloat162 t = __floats2bfloat162_rn(a, b);
    return *reinterpret_cast<uint32_t*>(&t);
}

#define SA 272
#define SJ 240
#define SAH (SA/2)   // 136 bf16 per row

__device__ __align__(16) float g_h[(size_t)NN*HD];
// Pre-baked W operands in smem-image Bt layout [n*SAH + k], 4 bufs:
// 0: W1 k=0..79, 1: W1 k=80..159, 2: W2, 3: W3
__device__ __align__(16) __nv_bfloat16 g_WH[4][128*SAH];
__device__ __align__(16) __nv_bfloat16 g_WL[4][128*SAH];

// ---------------------------------------------------------------------------
__global__ void __launch_bounds__(256) prepW_kernel(
    const float* __restrict__ W1, const float* __restrict__ W2,
    const float* __restrict__ W3)
{
    const int buf = blockIdx.y;
    const float* src; int K, koff;
    if      (buf == 0) { src = W1; K = 80;  koff = 0;  }
    else if (buf == 1) { src = W1; K = 80;  koff = 80; }
    else if (buf == 2) { src = W2; K = 128; koff = 0;  }
    else               { src = W3; K = 128; koff = 0;  }
    const int idx = blockIdx.x*256 + threadIdx.x;
    if (idx >= K*128) return;
    const int k = idx >> 7, n = idx & 127;
    float vh, vl; splitf(src[(size_t)(k + koff)*128 + n], vh, vl);
    g_WH[buf][n*SAH + k] = __float2bfloat16(vh);
    g_WL[buf][n*SAH + k] = __float2bfloat16(vl);
}

// Block-side W staging: pure vector copy of the baked image.
__device__ __forceinline__ void copyW(int buf, char* bH, char* bL, int tid)
{
    const uint4* sH = reinterpret_cast<const uint4*>(g_WH[buf]);
    const uint4* sL = reinterpret_cast<const uint4*>(g_WL[buf]);
    uint4* dH = reinterpret_cast<uint4*>(bH);
    uint4* dL = reinterpret_cast<uint4*>(bL);
#pragma unroll
    for (int i = tid; i < 128*SAH*2/16; i += 512) { dH[i] = sH[i]; dL[i] = sL[i]; }
}

// ---------------------------------------------------------------------------
// Warp GEMM: 16 rows x 64 cols per warp (nh = N-half).
// ---------------------------------------------------------------------------
template<int KS, int STRA>
__device__ __forceinline__ void gemm_mma(const char* aH, const char* aL,
                                         const char* bH, const char* bL,
                                         float (&acc)[8][4], int lane,
                                         int m0, int nh)
{
    const uint32_t aHu = smem_u32(aH), aLu = smem_u32(aL);
    const uint32_t bHu = smem_u32(bH), bLu = smem_u32(bL);
    const uint32_t offA = (uint32_t)(m0 + (lane & 15))*STRA + ((lane >> 4) << 4);
    const uint32_t offB = (uint32_t)(((lane >> 4) << 3) + (lane & 7))*SA
                        + (((lane >> 3) & 1) << 4)
                        + (uint32_t)nh*(4*16*SA);
#pragma unroll
    for (int ks = 0; ks < KS; ks++) {
        uint32_t ah[4], al[4];
        ldsm4(aHu + offA + ks*32, ah);
        ldsm4(aLu + offA + ks*32, al);
#pragma unroll
        for (int np = 0; np < 4; np++) {
            uint32_t bh[4], bl[4];
            ldsm4(bHu + offB + np*(16*SA) + ks*32, bh);
            ldsm4(bLu + offB + np*(16*SA) + ks*32, bl);
            mma16816(acc[2*np],   ah, bh[0], bh[1]);
            mma16816(acc[2*np],   al, bh[0], bh[1]);
            mma16816(acc[2*np],   ah, bl[0], bl[1]);
            mma16816(acc[2*np+1], ah, bh[2], bh[3]);
            mma16816(acc[2*np+1], al, bh[2], bh[3]);
            mma16816(acc[2*np+1], ah, bl[2], bl[3]);
        }
    }
}

__device__ __forceinline__ void zero_acc(float (&acc)[8][4]) {
#pragma unroll
    for (int i = 0; i < 8; i++)
#pragma unroll
        for (int j = 0; j < 4; j++) acc[i][j] = 0.f;
}

// Epilogue: D -> Bt (transposed) via stmatrix.trans; rows >= AA zeroed.
__device__ __forceinline__ void epi_T(float (&acc)[8][4], char* bH, char* bL,
                                      int lane, int m0, int c0)
{
    const int m = lane >> 3, s = lane & 7;
    const uint32_t off = (uint32_t)(c0 + 8*(m >> 1) + s)*SA + (m0 + 8*(m & 1))*2;
    const uint32_t bHu = smem_u32(bH) + off;
    const uint32_t bLu = smem_u32(bL) + off;
    const int r0 = m0 + (lane >> 2);
    const bool ok0 = r0 < AA, ok1 = (r0 + 8) < AA;
#pragma unroll
    for (int t = 0; t < 4; t++) {
        uint32_t hi[4], lo[4];
#pragma unroll
        for (int q = 0; q < 2; q++) {
            const float* a = acc[2*t + q];
            const float v0 = ok0 ? a[0] : 0.f;
            const float v1 = ok0 ? a[1] : 0.f;
            const float v2 = ok1 ? a[2] : 0.f;
            const float v3 = ok1 ? a[3] : 0.f;
            float h0, l0, h1, l1;
            splitf(v0, h0, l0); splitf(v1, h1, l1);
            hi[2*q]   = pkbf(h0, h1); lo[2*q]   = pkbf(l0, l1);
            splitf(v2, h0, l0); splitf(v3, h1, l1);
            hi[2*q+1] = pkbf(h0, h1); lo[2*q+1] = pkbf(l0, l1);
        }
        stsm4t(bHu + t*(16*SA), hi[0], hi[1], hi[2], hi[3]);
        stsm4t(bLu + t*(16*SA), lo[0], lo[1], lo[2], lo[3]);
    }
}

// Epilogue: H = relu(D + bias) -> A layout (stmatrix) or fp32 gmem (scalar).
template<bool TOGMEM>
__device__ __forceinline__ void epi_A(float (&acc)[8][4], const float* __restrict__ bias,
                                      char* aH, char* aL, float* __restrict__ gout,
                                      int lane, int m0, int c0)
{
    const int r0 = m0 + (lane >> 2), r1 = r0 + 8;
    const int nb = 2*(lane & 3);
    if (TOGMEM) {
#pragma unroll
        for (int nt = 0; nt < 8; nt++) {
            const int n0 = c0 + 8*nt + nb;
            const float b0 = bias[n0], b1 = bias[n0+1];
            float v00 = fmaxf(acc[nt][0] + b0, 0.f);
            float v01 = fmaxf(acc[nt][1] + b1, 0.f);
            float v10 = fmaxf(acc[nt][2] + b0, 0.f);
            float v11 = fmaxf(acc[nt][3] + b1, 0.f);
            if (r0 < AA) *reinterpret_cast<float2*>(gout + (size_t)r0*HD + n0) = make_float2(v00, v01);
            if (r1 < AA) *reinterpret_cast<float2*>(gout + (size_t)r1*HD + n0) = make_float2(v10, v11);
        }
        return;
    }
    const int m = lane >> 3, s = lane & 7;
    const uint32_t off = (uint32_t)(m0 + 8*(m & 1) + s)*SA + (c0 + 8*(m >> 1))*2;
    const uint32_t aHu = smem_u32(aH) + off;
    const uint32_t aLu = smem_u32(aL) + off;
    const bool ok0 = r0 < AA, ok1 = r1 < AA;
#pragma unroll
    for (int t = 0; t < 4; t++) {
        uint32_t hi[4], lo[4];
#pragma unroll
        for (int q = 0; q < 2; q++) {
            const int nt = 2*t + q;
            const int n0 = c0 + 8*nt + nb;
            const float b0 = bias[n0], b1 = bias[n0+1];
            float v00 = ok0 ? fmaxf(acc[nt][0] + b0, 0.f) : 0.f;
            float v01 = ok0 ? fmaxf(acc[nt][1] + b1, 0.f) : 0.f;
            float v10 = ok1 ? fmaxf(acc[nt][2] + b0, 0.f) : 0.f;
            float v11 = ok1 ? fmaxf(acc[nt][3] + b1, 0.f) : 0.f;
            float h0, l0, h1, l1;
            splitf(v00, h0, l0); splitf(v01, h1, l1);
            hi[2*q]   = pkbf(h0, h1); lo[2*q]   = pkbf(l0, l1);
            splitf(v10, h0, l0); splitf(v11, h1, l1);
            hi[2*q+1] = pkbf(h0, h1); lo[2*q+1] = pkbf(l0, l1);
        }
        stsm4(aHu + t*32, hi[0], hi[1], hi[2], hi[3]);
        stsm4(aLu + t*32, lo[0], lo[1], lo[2], lo[3]);
    }
}

// ---------------------------------------------------------------------------
__global__ void __launch_bounds__(512, 1) gcn_kernel(
    const float* __restrict__ x,
    const float* __restrict__ b1, const float* __restrict__ b2,
    const float* __restrict__ b3)
{
    extern __shared__ char smd[];
    char* sAh = smd;
    char* sAl = smd + 30464;
    char* sBh = smd + 60928;
    char* sBl = smd + 95744;
    char* sJh = smd + 130560;
    char* sJl = smd + 157440;

    __shared__ float xc[128][WIN];
    __shared__ float invd[128], dinv[128];

    const int g    = blockIdx.x;
    const int tid  = threadIdx.x;
    const int warp = tid >> 5;
    const int lane = tid & 31;
    const int wm   = warp >> 1;        // M-tile 0..7 (7 used)
    const int nh   = warp & 1;         // N-half 0/1
    const int m0   = wm * 16;
    const int c0   = nh * 64;
    const bool act = (wm < 7);         // 14 compute warps

    if (tid < AA) {
        float r[WIN]; float s = 0.f;
#pragma unroll
        for (int t = 0; t < WIN; t++) {
            r[t] = x[((size_t)(g*AA + tid)*WIN + t)*FDIM + (FDIM-1)]; s += r[t];
        }
        const float mean = s * (1.0f/WIN); float ss = 0.f;
#pragma unroll
        for (int t = 0; t < WIN; t++) { float v = r[t]-mean; xc[tid][t] = v; ss += v*v; }
        invd[tid] = rsqrtf(ss);
    } else if (tid < 128) {
        invd[tid] = 0.f;
#pragma unroll
        for (int t = 0; t < WIN; t++) xc[tid][t] = 0.f;
    }
    __syncthreads();

    // dinv: 4 threads per row (quad-split j), shuffle-quad reduce.
    {
        const int i = tid >> 2, q = tid & 3;
        float xi[WIN];
#pragma unroll
        for (int t = 0; t < WIN; t++) xi[t] = xc[i][t];
        const float di = invd[i];
        float rs = 0.f;
        const int j0 = q*25;
#pragma unroll 5
        for (int j = j0; j < j0 + 25; j++) {
            float dot = 0.f;
#pragma unroll
            for (int t = 0; t < WIN; t++) dot = fmaf(xi[t], xc[j][t], dot);
            rs += 1.0f - fabsf(dot * di * invd[j]);
        }
        rs += __shfl_xor_sync(0xffffffffu, rs, 1);
        rs += __shfl_xor_sync(0xffffffffu, rs, 2);
        if (q == 0 && i < AA) dinv[i] = rsqrtf(rs + 1.0f);
    }
    __syncthreads();

    for (int e = tid; e < MM*MM; e += 512) {
        const int i = e / MM, j = e - i*MM;
        float a = 0.f;
        if (i < AA && j < AA) {
            float dot = 0.f;
#pragma unroll
            for (int t = 0; t < WIN; t++) dot = fmaf(xc[i][t], xc[j][t], dot);
            float c = dot * invd[i] * invd[j];
            a = (1.0f - fabsf(c) + (i == j ? 1.0f : 0.0f)) * dinv[i] * dinv[j];
        }
        float vh, vl; splitf(a, vh, vl);
        const uint32_t o = (uint32_t)i*SJ + j*2;
        st_bf(sJh, o, vh); st_bf(sJl, o, vl);
    }

    float acc[8][4];
    zero_acc(acc);

#pragma unroll 1
    for (int c = 0; c < 2; c++) {
        __syncthreads();
        for (int idx = tid; idx < MM*80; idx += 512) {
            const int r = idx / 80, k = idx - r*80;
            float v = (r < AA) ? x[((size_t)(g*AA + r))*K1 + 80*c + k] : 0.f;
            float vh, vl; splitf(v, vh, vl);
            const uint32_t o = (uint32_t)r*SA + k*2;
            st_bf(sAh, o, vh); st_bf(sAl, o, vl);
        }
        copyW(c, sBh, sBl, tid);
        __syncthreads();
        if (act) gemm_mma<5, SA>(sAh, sAl, sBh, sBl, acc, lane, m0, nh);
    }
    __syncthreads();
    if (act) epi_T(acc, sBh, sBl, lane, m0, c0);
    __syncthreads();

    zero_acc(acc);
    if (act) gemm_mma<7, SJ>(sJh, sJl, sBh, sBl, acc, lane, m0, nh);
    __syncthreads();
    if (act) epi_A<false>(acc, b1, sAh, sAl, nullptr, lane, m0, c0);
    copyW(2, sBh, sBl, tid);
    __syncthreads();

    zero_acc(acc);
    if (act) gemm_mma<8, SA>(sAh, sAl, sBh, sBl, acc, lane, m0, nh);
    __syncthreads();
    if (act) epi_T(acc, sBh, sBl, lane, m0, c0);
    __syncthreads();

    zero_acc(acc);
    if (act) gemm_mma<7, SJ>(sJh, sJl, sBh, sBl, acc, lane, m0, nh);
    __syncthreads();
    if (act) epi_A<false>(acc, b2, sAh, sAl, nullptr, lane, m0, c0);
    copyW(3, sBh, sBl, tid);
    __syncthreads();

    zero_acc(acc);
    if (act) gemm_mma<8, SA>(sAh, sAl, sBh, sBl, acc, lane, m0, nh);
    __syncthreads();
    if (act) epi_T(acc, sBh, sBl, lane, m0, c0);
    __syncthreads();

    zero_acc(acc);
    if (act) gemm_mma<7, SJ>(sJh, sJl, sBh, sBl, acc, lane, m0, nh);
    if (act) epi_A<true>(acc, b3, nullptr, nullptr, g_h + (size_t)g*AA*HD, lane, m0, c0);
}

// ---------------------------------------------------------------------------
// conv1(relu)+conv2 fused, 1 row/warp; ReLU = add2(z, z&M), 0.5 folded into u.
// (Exact R13 form: 71.3us measured.)
// ---------------------------------------------------------------------------
__global__ void __launch_bounds__(256) conv_kernel(
    const float* __restrict__ cw1, const float* __restrict__ cb1,
    const float* __restrict__ cw2, const float* __restrict__ cb2,
    float* __restrict__ out)
{
    __shared__ ulonglong2 wpk[HD][4];
    const int tid = threadIdx.x;
    if (tid < HD) {
        const float wx = cw1[3*tid+0], wy = cw1[3*tid+1], wz = cw1[3*tid+2];
        const float wb = cb1[tid];
        const float u0 = 0.5f*cw2[3*tid+0], u1 = 0.5f*cw2[3*tid+1], u2 = 0.5f*cw2[3*tid+2];
        wpk[tid][0] = make_ulonglong2(pk2(wx, wx), pk2(wy, wy));
        wpk[tid][1] = make_ulonglong2(pk2(wz, wz), pk2(wb, wb));
        wpk[tid][2] = make_ulonglong2(pk2(u0, u0), pk2(u1, u1));
        wpk[tid][3] = make_ulonglong2(pk2(u2, u2), 0ull);
    }
    __syncthreads();

    const int warp = tid >> 5, lane = tid & 31;
    const int row  = blockIdx.x*8 + warp;

    const float4 hv = reinterpret_cast<const float4*>(g_h + (size_t)row*HD)[lane];
    float hm1 = __shfl_up_sync(0xffffffffu, hv.w, 1);  if (lane == 0)  hm1 = 0.f;
    float hp1 = __shfl_down_sync(0xffffffffu, hv.x, 1); if (lane == 31) hp1 = 0.f;

    const ull Pm = pk2(hm1,  hv.x);
    const ull P0 = pk2(hv.x, hv.y);
    const ull P1 = pk2(hv.y, hv.z);
    const ull P2 = pk2(hv.z, hv.w);
    const ull P3 = pk2(hv.w, hp1);
    const ull M = 0x7FFFFFFF7FFFFFFFull;

    ull T0a=0, T0b=0, T1a=0, T1b=0, T2a=0, T2b=0;
#pragma unroll 8
    for (int c = 0; c < HD; c++) {
        const ulonglong2 q0 = wpk[c][0];
        const ulonglong2 q1 = wpk[c][1];
        const ulonglong2 q2 = wpk[c][2];
        const ull        q3 = wpk[c][3].x;
        ull z01 = fma2(q0.x, Pm, fma2(q0.y, P0, fma2(q1.x, P1, q1.y)));
        ull z23 = fma2(q0.x, P1, fma2(q0.y, P2, fma2(q1.x, P3, q1.y)));
        z01 = add2(z01, z01 & M);   // 2*relu(z); 0.5 folded into u-weights
        z23 = add2(z23, z23 & M);
        T0a = fma2(q2.x, z01, T0a);  T0b = fma2(q2.x, z23, T0b);
        T1a = fma2(q2.y, z01, T1a);  T1b = fma2(q2.y, z23, T1b);
        T2a = fma2(q3,   z01, T2a);  T2b = fma2(q3,   z23, T2b);
    }
    const float2 t0a = upk2(T0a), t0b = upk2(T0b);
    const float2 t1a = upk2(T1a), t1b = upk2(T1b);
    const float2 t2a = upk2(T2a), t2b = upk2(T2b);

    float t0m = __shfl_up_sync(0xffffffffu, t0b.y, 1);  if (lane == 0)  t0m = 0.f;
    float t2p = __shfl_down_sync(0xffffffffu, t2a.x, 1); if (lane == 31) t2p = 0.f;

    const float c2 = cb2[0];
    float4 res;
    res.x = t0m   + t1a.x + t2a.y + c2;
    res.y = t0a.x + t1a.y + t2b.x + c2;
    res.z = t0a.y + t1b.x + t2b.y + c2;
    res.w = t0b.x + t1b.y + t2p   + c2;
    reinterpret_cast<float4*>(out + (size_t)row*HD)[lane] = res;
}

// ---------------------------------------------------------------------------
extern "C" void kernel_launch(void* const* d_in, const int* in_sizes, int n_in,
                              void* d_out, int out_size)
{
    const float* x   = (const float*)d_in[0];
    const float* W1  = (const float*)d_in[1];
    const float* b1  = (const float*)d_in[2];
    const float* W2  = (const float*)d_in[3];
    const float* b2  = (const float*)d_in[4];
    const float* W3  = (const float*)d_in[5];
    const float* b3  = (const float*)d_in[6];
    const float* cw1 = (const float*)d_in[7];
    const float* cb1 = (const float*)d_in[8];
    const float* cw2 = (const float*)d_in[9];
    const float* cb2 = (const float*)d_in[10];
    float* out = (float*)d_out;

    const int SMEM = 184320;
    cudaFuncSetAttribute(gcn_kernel, cudaFuncAttributeMaxDynamicSharedMemorySize, SMEM);

    dim3 pgrid(64, 4);
    prepW_kernel<<<pgrid, 256>>>(W1, W2, W3);
    gcn_kernel<<<GG, 512, SMEM>>>(x, b1, b2, b3);
    conv_kernel<<<NN/8, 256>>>(cw1, cb1, cw2, cb2, out);
}

// round 16
// speedup vs baseline: 1.5910x; 1.5910x over previous
#include <cuda_runtime.h>
#include <cuda_bf16.h>
#include <cstdint>

#define GG   128
#define AA   100
#define WIN  10
#define FDIM 16
#define HD   128
#define K1   (WIN*FDIM)   // 160
#define NN   (GG*AA)
#define MM   112          // padded M (100 -> 112)

typedef unsigned long long ull;

// ===== f32x2 helpers (conv kernel) =====
__device__ __forceinline__ ull pk2(float lo, float hi) {
    ull r; asm("mov.b64 %0, {%1,%2};" : "=l"(r) : "f"(lo), "f"(hi)); return r;
}
__device__ __forceinline__ ull fma2(ull a, ull b, ull c) {
    ull d; asm("fma.rn.f32x2 %0, %1, %2, %3;" : "=l"(d) : "l"(a), "l"(b), "l"(c)); return d;
}
__device__ __forceinline__ ull add2(ull a, ull b) {
    ull d; asm("add.rn.f32x2 %0, %1, %2;" : "=l"(d) : "l"(a), "l"(b)); return d;
}
__device__ __forceinline__ float2 upk2(ull v) {
    float lo, hi; asm("mov.b64 {%0,%1}, %2;" : "=f"(lo), "=f"(hi) : "l"(v));
    return make_float2(lo, hi);
}

// ===== mma/ldmatrix/stmatrix helpers =====
__device__ __forceinline__ uint32_t smem_u32(const void* p) {
    uint32_t a; asm("{ .reg .u64 t; cvta.to.shared.u64 t, %1; cvt.u32.u64 %0, t; }"
                    : "=r"(a) : "l"(p)); return a;
}
__device__ __forceinline__ void ldsm4(uint32_t addr, uint32_t r[4]) {
    asm volatile("ldmatrix.sync.aligned.m8n8.x4.shared.b16 {%0,%1,%2,%3}, [%4];"
        : "=r"(r[0]), "=r"(r[1]), "=r"(r[2]), "=r"(r[3]) : "r"(addr));
}
__device__ __forceinline__ void stsm4t(uint32_t addr, uint32_t x0, uint32_t x1,
                                       uint32_t x2, uint32_t x3) {
    asm volatile("stmatrix.sync.aligned.m8n8.x4.trans.shared.b16 [%0], {%1,%2,%3,%4};"
        :: "r"(addr), "r"(x0), "r"(x1), "r"(x2), "r"(x3) : "memory");
}
__device__ __forceinline__ void stsm4(uint32_t addr, uint32_t x0, uint32_t x1,
                                      uint32_t x2, uint32_t x3) {
    asm volatile("stmatrix.sync.aligned.m8n8.x4.shared.b16 [%0], {%1,%2,%3,%4};"
        :: "r"(addr), "r"(x0), "r"(x1), "r"(x2), "r"(x3) : "memory");
}
__device__ __forceinline__ void mma16816(float* c, const uint32_t a[4],
                                         uint32_t b0, uint32_t b1) {
    asm volatile("mma.sync.aligned.m16n8k16.row.col.f32.bf16.bf16.f32 "
        "{%0,%1,%2,%3}, {%4,%5,%6,%7}, {%8,%9}, {%0,%1,%2,%3};"
        : "+f"(c[0]), "+f"(c[1]), "+f"(c[2]), "+f"(c[3])
        : "r"(a[0]), "r"(a[1]), "r"(a[2]), "r"(a[3]), "r"(b0), "r"(b1));
}
__device__ __forceinline__ void splitf(float v, float& vh, float& vl) {
    vh = __bfloat162float(__float2bfloat16(v)); vl = v - vh;
}
__device__ __forceinline__ void st_bf(char* base, uint32_t off, float v) {
    *reinterpret_cast<__nv_bfloat16*>(base + off) = __float2bfloat16(v);
}
__device__ __forceinline__ uint32_t pkbf(float a, float b) {
    __nv_bfloat162 t = __floats2bfloat162_rn(a, b);
    return *reinterpret_cast<uint32_t*>(&t);
}

#define SA 272
#define SJ 240

__device__ __align__(16) float g_h[(size_t)NN*HD];

// ---------------------------------------------------------------------------
// Warp GEMM: 16 rows x 64 cols per warp (nh = N-half).
// ---------------------------------------------------------------------------
template<int KS, int STRA>
__device__ __forceinline__ void gemm_mma(const char* aH, const char* aL,
                                         const char* bH, const char* bL,
                                         float (&acc)[8][4], int lane,
                                         int m0, int nh)
{
    const uint32_t aHu = smem_u32(aH), aLu = smem_u32(aL);
    const uint32_t bHu = smem_u32(bH), bLu = smem_u32(bL);
    const uint32_t offA = (uint32_t)(m0 + (lane & 15))*STRA + ((lane >> 4) << 4);
    const uint32_t offB = (uint32_t)(((lane >> 4) << 3) + (lane & 7))*SA
                        + (((lane >> 3) & 1) << 4)
                        + (uint32_t)nh*(4*16*SA);
#pragma unroll
    for (int ks = 0; ks < KS; ks++) {
        uint32_t ah[4], al[4];
        ldsm4(aHu + offA + ks*32, ah);
        ldsm4(aLu + offA + ks*32, al);
#pragma unroll
        for (int np = 0; np < 4; np++) {
            uint32_t bh[4], bl[4];
            ldsm4(bHu + offB + np*(16*SA) + ks*32, bh);
            ldsm4(bLu + offB + np*(16*SA) + ks*32, bl);
            mma16816(acc[2*np],   ah, bh[0], bh[1]);
            mma16816(acc[2*np],   al, bh[0], bh[1]);
            mma16816(acc[2*np],   ah, bl[0], bl[1]);
            mma16816(acc[2*np+1], ah, bh[2], bh[3]);
            mma16816(acc[2*np+1], al, bh[2], bh[3]);
            mma16816(acc[2*np+1], ah, bl[2], bl[3]);
        }
    }
}

__device__ __forceinline__ void zero_acc(float (&acc)[8][4]) {
#pragma unroll
    for (int i = 0; i < 8; i++)
#pragma unroll
        for (int j = 0; j < 4; j++) acc[i][j] = 0.f;
}

// Epilogue: D -> Bt (transposed) via stmatrix.trans; rows >= AA zeroed.
__device__ __forceinline__ void epi_T(float (&acc)[8][4], char* bH, char* bL,
                                      int lane, int m0, int c0)
{
    const int m = lane >> 3, s = lane & 7;
    const uint32_t off = (uint32_t)(c0 + 8*(m >> 1) + s)*SA + (m0 + 8*(m & 1))*2;
    const uint32_t bHu = smem_u32(bH) + off;
    const uint32_t bLu = smem_u32(bL) + off;
    const int r0 = m0 + (lane >> 2);
    const bool ok0 = r0 < AA, ok1 = (r0 + 8) < AA;
#pragma unroll
    for (int t = 0; t < 4; t++) {
        uint32_t hi[4], lo[4];
#pragma unroll
        for (int q = 0; q < 2; q++) {
            const float* a = acc[2*t + q];
            const float v0 = ok0 ? a[0] : 0.f;
            const float v1 = ok0 ? a[1] : 0.f;
            const float v2 = ok1 ? a[2] : 0.f;
            const float v3 = ok1 ? a[3] : 0.f;
            float h0, l0, h1, l1;
            splitf(v0, h0, l0); splitf(v1, h1, l1);
            hi[2*q]   = pkbf(h0, h1); lo[2*q]   = pkbf(l0, l1);
            splitf(v2, h0, l0); splitf(v3, h1, l1);
            hi[2*q+1] = pkbf(h0, h1); lo[2*q+1] = pkbf(l0, l1);
        }
        stsm4t(bHu + t*(16*SA), hi[0], hi[1], hi[2], hi[3]);
        stsm4t(bLu + t*(16*SA), lo[0], lo[1], lo[2], lo[3]);
    }
}

// Epilogue: H = relu(D + bias) -> A layout (stmatrix) or fp32 gmem (scalar).
template<bool TOGMEM>
__device__ __forceinline__ void epi_A(float (&acc)[8][4], const float* __restrict__ bias,
                                      char* aH, char* aL, float* __restrict__ gout,
                                      int lane, int m0, int c0)
{
    const int r0 = m0 + (lane >> 2), r1 = r0 + 8;
    const int nb = 2*(lane & 3);
    if (TOGMEM) {
#pragma unroll
        for (int nt = 0; nt < 8; nt++) {
            const int n0 = c0 + 8*nt + nb;
            const float b0 = bias[n0], b1 = bias[n0+1];
            float v00 = fmaxf(acc[nt][0] + b0, 0.f);
            float v01 = fmaxf(acc[nt][1] + b1, 0.f);
            float v10 = fmaxf(acc[nt][2] + b0, 0.f);
            float v11 = fmaxf(acc[nt][3] + b1, 0.f);
            if (r0 < AA) *reinterpret_cast<float2*>(gout + (size_t)r0*HD + n0) = make_float2(v00, v01);
            if (r1 < AA) *reinterpret_cast<float2*>(gout + (size_t)r1*HD + n0) = make_float2(v10, v11);
        }
        return;
    }
    const int m = lane >> 3, s = lane & 7;
    const uint32_t off = (uint32_t)(m0 + 8*(m & 1) + s)*SA + (c0 + 8*(m >> 1))*2;
    const uint32_t aHu = smem_u32(aH) + off;
    const uint32_t aLu = smem_u32(aL) + off;
    const bool ok0 = r0 < AA, ok1 = r1 < AA;
#pragma unroll
    for (int t = 0; t < 4; t++) {
        uint32_t hi[4], lo[4];
#pragma unroll
        for (int q = 0; q < 2; q++) {
            const int nt = 2*t + q;
            const int n0 = c0 + 8*nt + nb;
            const float b0 = bias[n0], b1 = bias[n0+1];
            float v00 = ok0 ? fmaxf(acc[nt][0] + b0, 0.f) : 0.f;
            float v01 = ok0 ? fmaxf(acc[nt][1] + b1, 0.f) : 0.f;
            float v10 = ok1 ? fmaxf(acc[nt][2] + b0, 0.f) : 0.f;
            float v11 = ok1 ? fmaxf(acc[nt][3] + b1, 0.f) : 0.f;
            float h0, l0, h1, l1;
            splitf(v00, h0, l0); splitf(v01, h1, l1);
            hi[2*q]   = pkbf(h0, h1); lo[2*q]   = pkbf(l0, l1);
            splitf(v10, h0, l0); splitf(v11, h1, l1);
            hi[2*q+1] = pkbf(h0, h1); lo[2*q+1] = pkbf(l0, l1);
        }
        stsm4(aHu + t*32, hi[0], hi[1], hi[2], hi[3]);
        stsm4(aLu + t*32, lo[0], lo[1], lo[2], lo[3]);
    }
}

// Stage W^T into Bt[n][k] hi/lo, processing k-PAIRS (one STS.32 per buf).
__device__ __forceinline__ void stageW(const float* __restrict__ W, int K,
                                       char* bH, char* bL, int tid)
{
    const int tot = (K/2)*128;
    for (int idx = tid; idx < tot; idx += 512) {
        const int kp = idx >> 7, n = idx & 127;
        const float v0 = W[(size_t)(2*kp)*128 + n];
        const float v1 = W[(size_t)(2*kp+1)*128 + n];
        float h0, l0, h1, l1;
        splitf(v0, h0, l0); splitf(v1, h1, l1);
        const uint32_t o = (uint32_t)n*SA + kp*4;
        *reinterpret_cast<uint32_t*>(bH + o) = pkbf(h0, h1);
        *reinterpret_cast<uint32_t*>(bL + o) = pkbf(l0, l1);
    }
}

// ---------------------------------------------------------------------------
__global__ void __launch_bounds__(512, 1) gcn_kernel(
    const float* __restrict__ x,
    const float* __restrict__ W1, const float* __restrict__ b1,
    const float* __restrict__ W2, const float* __restrict__ b2,
    const float* __restrict__ W3, const float* __restrict__ b3)
{
    extern __shared__ char smd[];
    char* sAh = smd;
    char* sAl = smd + 30464;
    char* sBh = smd + 60928;
    char* sBl = smd + 95744;
    char* sJh = smd + 130560;
    char* sJl = smd + 157440;

    __shared__ float xc[128][WIN];
    __shared__ float invd[128], dinv[128];

    const int g    = blockIdx.x;
    const int tid  = threadIdx.x;
    const int warp = tid >> 5;
    const int lane = tid & 31;
    const int wm   = warp >> 1;        // M-tile 0..7 (7 used)
    const int nh   = warp & 1;         // N-half 0/1
    const int m0   = wm * 16;
    const int c0   = nh * 64;
    const bool act = (wm < 7);         // 14 compute warps

    if (tid < AA) {
        float r[WIN]; float s = 0.f;
#pragma unroll
        for (int t = 0; t < WIN; t++) {
            r[t] = x[((size_t)(g*AA + tid)*WIN + t)*FDIM + (FDIM-1)]; s += r[t];
        }
        const float mean = s * (1.0f/WIN); float ss = 0.f;
#pragma unroll
        for (int t = 0; t < WIN; t++) { float v = r[t]-mean; xc[tid][t] = v; ss += v*v; }
        invd[tid] = rsqrtf(ss);
    } else if (tid < 128) {
        invd[tid] = 0.f;
#pragma unroll
        for (int t = 0; t < WIN; t++) xc[tid][t] = 0.f;
    }
    __syncthreads();

    // dinv: 4 threads per row (quad-split j), shuffle-quad reduce.
    {
        const int i = tid >> 2, q = tid & 3;
        float xi[WIN];
#pragma unroll
        for (int t = 0; t < WIN; t++) xi[t] = xc[i][t];
        const float di = invd[i];
        float rs = 0.f;
        const int j0 = q*25;
#pragma unroll 5
        for (int j = j0; j < j0 + 25; j++) {
            float dot = 0.f;
#pragma unroll
            for (int t = 0; t < WIN; t++) dot = fmaf(xi[t], xc[j][t], dot);
            rs += 1.0f - fabsf(dot * di * invd[j]);
        }
        rs += __shfl_xor_sync(0xffffffffu, rs, 1);
        rs += __shfl_xor_sync(0xffffffffu, rs, 2);
        if (q == 0 && i < AA) dinv[i] = rsqrtf(rs + 1.0f);
    }
    __syncthreads();

    // Adjacency staging: j-pairs, one STS.32 per buffer per pair.
    for (int e = tid; e < MM*(MM/2); e += 512) {
        const int i = e / (MM/2), jp = e - i*(MM/2);
        const int j0 = 2*jp, j1 = j0 + 1;
        float a0 = 0.f, a1 = 0.f;
        if (i < AA) {
            float xi[WIN];
#pragma unroll
            for (int t = 0; t < WIN; t++) xi[t] = xc[i][t];
            if (j0 < AA) {
                float dot = 0.f;
#pragma unroll
                for (int t = 0; t < WIN; t++) dot = fmaf(xi[t], xc[j0][t], dot);
                float c = dot * invd[i] * invd[j0];
                a0 = (1.0f - fabsf(c) + (i == j0 ? 1.0f : 0.0f)) * dinv[i] * dinv[j0];
            }
            if (j1 < AA) {
                float dot = 0.f;
#pragma unroll
                for (int t = 0; t < WIN; t++) dot = fmaf(xi[t], xc[j1][t], dot);
                float c = dot * invd[i] * invd[j1];
                a1 = (1.0f - fabsf(c) + (i == j1 ? 1.0f : 0.0f)) * dinv[i] * dinv[j1];
            }
        }
        float h0, l0, h1, l1;
        splitf(a0, h0, l0); splitf(a1, h1, l1);
        const uint32_t o = (uint32_t)i*SJ + j0*2;
        *reinterpret_cast<uint32_t*>(sJh + o) = pkbf(h0, h1);
        *reinterpret_cast<uint32_t*>(sJl + o) = pkbf(l0, l1);
    }

    float acc[8][4];
    zero_acc(acc);

#pragma unroll 1
    for (int c = 0; c < 2; c++) {
        __syncthreads();
        // x staging: k-pairs via float2 loads, one STS.32 per buffer.
        for (int idx = tid; idx < MM*40; idx += 512) {
            const int r = idx / 40, kp = idx - r*40;
            float2 v = make_float2(0.f, 0.f);
            if (r < AA)
                v = *reinterpret_cast<const float2*>(
                        x + ((size_t)(g*AA + r))*K1 + 80*c + 2*kp);
            float h0, l0, h1, l1;
            splitf(v.x, h0, l0); splitf(v.y, h1, l1);
            const uint32_t o = (uint32_t)r*SA + kp*4;
            *reinterpret_cast<uint32_t*>(sAh + o) = pkbf(h0, h1);
            *reinterpret_cast<uint32_t*>(sAl + o) = pkbf(l0, l1);
        }
        stageW(W1 + (size_t)80*c*128, 80, sBh, sBl, tid);
        __syncthreads();
        if (act) gemm_mma<5, SA>(sAh, sAl, sBh, sBl, acc, lane, m0, nh);
    }
    __syncthreads();
    if (act) epi_T(acc, sBh, sBl, lane, m0, c0);
    __syncthreads();

    zero_acc(acc);
    if (act) gemm_mma<7, SJ>(sJh, sJl, sBh, sBl, acc, lane, m0, nh);
    __syncthreads();
    if (act) epi_A<false>(acc, b1, sAh, sAl, nullptr, lane, m0, c0);
    stageW(W2, HD, sBh, sBl, tid);
    __syncthreads();

    zero_acc(acc);
    if (act) gemm_mma<8, SA>(sAh, sAl, sBh, sBl, acc, lane, m0, nh);
    __syncthreads();
    if (act) epi_T(acc, sBh, sBl, lane, m0, c0);
    __syncthreads();

    zero_acc(acc);
    if (act) gemm_mma<7, SJ>(sJh, sJl, sBh, sBl, acc, lane, m0, nh);
    __syncthreads();
    if (act) epi_A<false>(acc, b2, sAh, sAl, nullptr, lane, m0, c0);
    stageW(W3, HD, sBh, sBl, tid);
    __syncthreads();

    zero_acc(acc);
    if (act) gemm_mma<8, SA>(sAh, sAl, sBh, sBl, acc, lane, m0, nh);
    __syncthreads();
    if (act) epi_T(acc, sBh, sBl, lane, m0, c0);
    __syncthreads();

    zero_acc(acc);
    if (act) gemm_mma<7, SJ>(sJh, sJl, sBh, sBl, acc, lane, m0, nh);
    if (act) epi_A<true>(acc, b3, nullptr, nullptr, g_h + (size_t)g*AA*HD, lane, m0, c0);
}

// ---------------------------------------------------------------------------
// conv1(relu)+conv2 fused, 1 row/warp; ReLU = add2(z, z&M), 0.5 folded into u.
// (Exact R13 form: 71.3us measured.)
// ---------------------------------------------------------------------------
__global__ void __launch_bounds__(256) conv_kernel(
    const float* __restrict__ cw1, const float* __restrict__ cb1,
    const float* __restrict__ cw2, const float* __restrict__ cb2,
    float* __restrict__ out)
{
    __shared__ ulonglong2 wpk[HD][4];
    const int tid = threadIdx.x;
    if (tid < HD) {
        const float wx = cw1[3*tid+0], wy = cw1[3*tid+1], wz = cw1[3*tid+2];
        const float wb = cb1[tid];
        const float u0 = 0.5f*cw2[3*tid+0], u1 = 0.5f*cw2[3*tid+1], u2 = 0.5f*cw2[3*tid+2];
        wpk[tid][0] = make_ulonglong2(pk2(wx, wx), pk2(wy, wy));
        wpk[tid][1] = make_ulonglong2(pk2(wz, wz), pk2(wb, wb));
        wpk[tid][2] = make_ulonglong2(pk2(u0, u0), pk2(u1, u1));
        wpk[tid][3] = make_ulonglong2(pk2(u2, u2), 0ull);
    }
    __syncthreads();

    const int warp = tid >> 5, lane = tid & 31;
    const int row  = blockIdx.x*8 + warp;

    const float4 hv = reinterpret_cast<const float4*>(g_h + (size_t)row*HD)[lane];
    float hm1 = __shfl_up_sync(0xffffffffu, hv.w, 1);  if (lane == 0)  hm1 = 0.f;
    float hp1 = __shfl_down_sync(0xffffffffu, hv.x, 1); if (lane == 31) hp1 = 0.f;

    const ull Pm = pk2(hm1,  hv.x);
    const ull P0 = pk2(hv.x, hv.y);
    const ull P1 = pk2(hv.y, hv.z);
    const ull P2 = pk2(hv.z, hv.w);
    const ull P3 = pk2(hv.w, hp1);
    const ull M = 0x7FFFFFFF7FFFFFFFull;

    ull T0a=0, T0b=0, T1a=0, T1b=0, T2a=0, T2b=0;
#pragma unroll 8
    for (int c = 0; c < HD; c++) {
        const ulonglong2 q0 = wpk[c][0];
        const ulonglong2 q1 = wpk[c][1];
        const ulonglong2 q2 = wpk[c][2];
        const ull        q3 = wpk[c][3].x;
        ull z01 = fma2(q0.x, Pm, fma2(q0.y, P0, fma2(q1.x, P1, q1.y)));
        ull z23 = fma2(q0.x, P1, fma2(q0.y, P2, fma2(q1.x, P3, q1.y)));
        z01 = add2(z01, z01 & M);   // 2*relu(z); 0.5 folded into u-weights
        z23 = add2(z23, z23 & M);
        T0a = fma2(q2.x, z01, T0a);  T0b = fma2(q2.x, z23, T0b);
        T1a = fma2(q2.y, z01, T1a);  T1b = fma2(q2.y, z23, T1b);
        T2a = fma2(q3,   z01, T2a);  T2b = fma2(q3,   z23, T2b);
    }
    const float2 t0a = upk2(T0a), t0b = upk2(T0b);
    const float2 t1a = upk2(T1a), t1b = upk2(T1b);
    const float2 t2a = upk2(T2a), t2b = upk2(T2b);

    float t0m = __shfl_up_sync(0xffffffffu, t0b.y, 1);  if (lane == 0)  t0m = 0.f;
    float t2p = __shfl_down_sync(0xffffffffu, t2a.x, 1); if (lane == 31) t2p = 0.f;

    const float c2 = cb2[0];
    float4 res;
    res.x = t0m   + t1a.x + t2a.y + c2;
    res.y = t0a.x + t1a.y + t2b.x + c2;
    res.z = t0a.y + t1b.x + t2b.y + c2;
    res.w = t0b.x + t1b.y + t2p   + c2;
    reinterpret_cast<float4*>(out + (size_t)row*HD)[lane] = res;
}

// ---------------------------------------------------------------------------
extern "C" void kernel_launch(void* const* d_in, const int* in_sizes, int n_in,
                              void* d_out, int out_size)
{
    const float* x   = (const float*)d_in[0];
    const float* W1  = (const float*)d_in[1];
    const float* b1  = (const float*)d_in[2];
    const float* W2  = (const float*)d_in[3];
    const float* b2  = (const float*)d_in[4];
    const float* W3  = (const float*)d_in[5];
    const float* b3  = (const float*)d_in[6];
    const float* cw1 = (const float*)d_in[7];
    const float* cb1 = (const float*)d_in[8];
    const float* cw2 = (const float*)d_in[9];
    const float* cb2 = (const float*)d_in[10];
    float* out = (float*)d_out;

    const int SMEM = 184320;
    cudaFuncSetAttribute(gcn_kernel, cudaFuncAttributeMaxDynamicSharedMemorySize, SMEM);

    gcn_kernel<<<GG, 512, SMEM>>>(x, W1, b1, W2, b2, W3, b3);
    conv_kernel<<<NN/8, 256>>>(cw1, cb1, cw2, cb2, out);
}

// round 17
// speedup vs baseline: 1.7066x; 1.0726x over previous
#include <cuda_runtime.h>
#include <cuda_bf16.h>
#include <cstdint>

#define GG   128
#define AA   100
#define WIN  10
#define FDIM 16
#define HD   128
#define K1   (WIN*FDIM)   // 160
#define NN   (GG*AA)
#define MM   112          // padded M (100 -> 112)

typedef unsigned long long ull;

// ===== f32x2 helpers (conv kernel) =====
__device__ __forceinline__ ull pk2(float lo, float hi) {
    ull r; asm("mov.b64 %0, {%1,%2};" : "=l"(r) : "f"(lo), "f"(hi)); return r;
}
__device__ __forceinline__ ull fma2(ull a, ull b, ull c) {
    ull d; asm("fma.rn.f32x2 %0, %1, %2, %3;" : "=l"(d) : "l"(a), "l"(b), "l"(c)); return d;
}
__device__ __forceinline__ ull add2(ull a, ull b) {
    ull d; asm("add.rn.f32x2 %0, %1, %2;" : "=l"(d) : "l"(a), "l"(b)); return d;
}
__device__ __forceinline__ float2 upk2(ull v) {
    float lo, hi; asm("mov.b64 {%0,%1}, %2;" : "=f"(lo), "=f"(hi) : "l"(v));
    return make_float2(lo, hi);
}

// ===== mma/ldmatrix/stmatrix helpers =====
__device__ __forceinline__ uint32_t smem_u32(const void* p) {
    uint32_t a; asm("{ .reg .u64 t; cvta.to.shared.u64 t, %1; cvt.u32.u64 %0, t; }"
                    : "=r"(a) : "l"(p)); return a;
}
__device__ __forceinline__ void ldsm4(uint32_t addr, uint32_t r[4]) {
    asm volatile("ldmatrix.sync.aligned.m8n8.x4.shared.b16 {%0,%1,%2,%3}, [%4];"
        : "=r"(r[0]), "=r"(r[1]), "=r"(r[2]), "=r"(r[3]) : "r"(addr));
}
__device__ __forceinline__ void stsm4t(uint32_t addr, uint32_t x0, uint32_t x1,
                                       uint32_t x2, uint32_t x3) {
    asm volatile("stmatrix.sync.aligned.m8n8.x4.trans.shared.b16 [%0], {%1,%2,%3,%4};"
        :: "r"(addr), "r"(x0), "r"(x1), "r"(x2), "r"(x3) : "memory");
}
__device__ __forceinline__ void stsm4(uint32_t addr, uint32_t x0, uint32_t x1,
                                      uint32_t x2, uint32_t x3) {
    asm volatile("stmatrix.sync.aligned.m8n8.x4.shared.b16 [%0], {%1,%2,%3,%4};"
        :: "r"(addr), "r"(x0), "r"(x1), "r"(x2), "r"(x3) : "memory");
}
__device__ __forceinline__ void mma16816(float* c, const uint32_t a[4],
                                         uint32_t b0, uint32_t b1) {
    asm volatile("mma.sync.aligned.m16n8k16.row.col.f32.bf16.bf16.f32 "
        "{%0,%1,%2,%3}, {%4,%5,%6,%7}, {%8,%9}, {%0,%1,%2,%3};"
        : "+f"(c[0]), "+f"(c[1]), "+f"(c[2]), "+f"(c[3])
        : "r"(a[0]), "r"(a[1]), "r"(a[2]), "r"(a[3]), "r"(b0), "r"(b1));
}
__device__ __forceinline__ void splitf(float v, float& vh, float& vl) {
    vh = __bfloat162float(__float2bfloat16(v)); vl = v - vh;
}
__device__ __forceinline__ void st_bf(char* base, uint32_t off, float v) {
    *reinterpret_cast<__nv_bfloat16*>(base + off) = __float2bfloat16(v);
}
__device__ __forceinline__ uint32_t pkbf(float a, float b) {
    __nv_bfloat162 t = __floats2bfloat162_rn(a, b);
    return *reinterpret_cast<uint32_t*>(&t);
}

#define SA 272
#define SJ 240

__device__ __align__(16) float g_h[(size_t)NN*HD];
// conv weights, dup-packed, staged via constant memory (LDCU -> UR operands)
__constant__ __align__(16) ull c_wpk[HD*8];
__device__   __align__(16) ull g_wtmp[HD*8];

// ---------------------------------------------------------------------------
__global__ void packW_kernel(const float* __restrict__ cw1,
                             const float* __restrict__ cb1,
                             const float* __restrict__ cw2)
{
    const int c = threadIdx.x;
    if (c < HD) {
        const float wx = cw1[3*c+0], wy = cw1[3*c+1], wz = cw1[3*c+2];
        const float wb = cb1[c];
        const float u0 = 0.5f*cw2[3*c+0], u1 = 0.5f*cw2[3*c+1], u2 = 0.5f*cw2[3*c+2];
        g_wtmp[c*8+0] = pk2(wx, wx);
        g_wtmp[c*8+1] = pk2(wy, wy);
        g_wtmp[c*8+2] = pk2(wz, wz);
        g_wtmp[c*8+3] = pk2(wb, wb);
        g_wtmp[c*8+4] = pk2(u0, u0);
        g_wtmp[c*8+5] = pk2(u1, u1);
        g_wtmp[c*8+6] = pk2(u2, u2);
        g_wtmp[c*8+7] = 0ull;
    }
}

// ---------------------------------------------------------------------------
// Warp GEMM: 16 rows x 64 cols per warp (nh = N-half).
// ---------------------------------------------------------------------------
template<int KS, int STRA>
__device__ __forceinline__ void gemm_mma(const char* aH, const char* aL,
                                         const char* bH, const char* bL,
                                         float (&acc)[8][4], int lane,
                                         int m0, int nh)
{
    const uint32_t aHu = smem_u32(aH), aLu = smem_u32(aL);
    const uint32_t bHu = smem_u32(bH), bLu = smem_u32(bL);
    const uint32_t offA = (uint32_t)(m0 + (lane & 15))*STRA + ((lane >> 4) << 4);
    const uint32_t offB = (uint32_t)(((lane >> 4) << 3) + (lane & 7))*SA
                        + (((lane >> 3) & 1) << 4)
                        + (uint32_t)nh*(4*16*SA);
#pragma unroll
    for (int ks = 0; ks < KS; ks++) {
        uint32_t ah[4], al[4];
        ldsm4(aHu + offA + ks*32, ah);
        ldsm4(aLu + offA + ks*32, al);
#pragma unroll
        for (int np = 0; np < 4; np++) {
            uint32_t bh[4], bl[4];
            ldsm4(bHu + offB + np*(16*SA) + ks*32, bh);
            ldsm4(bLu + offB + np*(16*SA) + ks*32, bl);
            mma16816(acc[2*np],   ah, bh[0], bh[1]);
            mma16816(acc[2*np],   al, bh[0], bh[1]);
            mma16816(acc[2*np],   ah, bl[0], bl[1]);
            mma16816(acc[2*np+1], ah, bh[2], bh[3]);
            mma16816(acc[2*np+1], al, bh[2], bh[3]);
            mma16816(acc[2*np+1], ah, bl[2], bl[3]);
        }
    }
}

__device__ __forceinline__ void zero_acc(float (&acc)[8][4]) {
#pragma unroll
    for (int i = 0; i < 8; i++)
#pragma unroll
        for (int j = 0; j < 4; j++) acc[i][j] = 0.f;
}

// Epilogue: D -> Bt (transposed) via stmatrix.trans; rows >= AA zeroed.
__device__ __forceinline__ void epi_T(float (&acc)[8][4], char* bH, char* bL,
                                      int lane, int m0, int c0)
{
    const int m = lane >> 3, s = lane & 7;
    const uint32_t off = (uint32_t)(c0 + 8*(m >> 1) + s)*SA + (m0 + 8*(m & 1))*2;
    const uint32_t bHu = smem_u32(bH) + off;
    const uint32_t bLu = smem_u32(bL) + off;
    const int r0 = m0 + (lane >> 2);
    const bool ok0 = r0 < AA, ok1 = (r0 + 8) < AA;
#pragma unroll
    for (int t = 0; t < 4; t++) {
        uint32_t hi[4], lo[4];
#pragma unroll
        for (int q = 0; q < 2; q++) {
            const float* a = acc[2*t + q];
            const float v0 = ok0 ? a[0] : 0.f;
            const float v1 = ok0 ? a[1] : 0.f;
            const float v2 = ok1 ? a[2] : 0.f;
            const float v3 = ok1 ? a[3] : 0.f;
            float h0, l0, h1, l1;
            splitf(v0, h0, l0); splitf(v1, h1, l1);
            hi[2*q]   = pkbf(h0, h1); lo[2*q]   = pkbf(l0, l1);
            splitf(v2, h0, l0); splitf(v3, h1, l1);
            hi[2*q+1] = pkbf(h0, h1); lo[2*q+1] = pkbf(l0, l1);
        }
        stsm4t(bHu + t*(16*SA), hi[0], hi[1], hi[2], hi[3]);
        stsm4t(bLu + t*(16*SA), lo[0], lo[1], lo[2], lo[3]);
    }
}

// Epilogue: H = relu(D + bias) -> A layout (stmatrix) or fp32 gmem (scalar).
template<bool TOGMEM>
__device__ __forceinline__ void epi_A(float (&acc)[8][4], const float* __restrict__ bias,
                                      char* aH, char* aL, float* __restrict__ gout,
                                      int lane, int m0, int c0)
{
    const int r0 = m0 + (lane >> 2), r1 = r0 + 8;
    const int nb = 2*(lane & 3);
    if (TOGMEM) {
#pragma unroll
        for (int nt = 0; nt < 8; nt++) {
            const int n0 = c0 + 8*nt + nb;
            const float b0 = bias[n0], b1 = bias[n0+1];
            float v00 = fmaxf(acc[nt][0] + b0, 0.f);
            float v01 = fmaxf(acc[nt][1] + b1, 0.f);
            float v10 = fmaxf(acc[nt][2] + b0, 0.f);
            float v11 = fmaxf(acc[nt][3] + b1, 0.f);
            if (r0 < AA) *reinterpret_cast<float2*>(gout + (size_t)r0*HD + n0) = make_float2(v00, v01);
            if (r1 < AA) *reinterpret_cast<float2*>(gout + (size_t)r1*HD + n0) = make_float2(v10, v11);
        }
        return;
    }
    const int m = lane >> 3, s = lane & 7;
    const uint32_t off = (uint32_t)(m0 + 8*(m & 1) + s)*SA + (c0 + 8*(m >> 1))*2;
    const uint32_t aHu = smem_u32(aH) + off;
    const uint32_t aLu = smem_u32(aL) + off;
    const bool ok0 = r0 < AA, ok1 = r1 < AA;
#pragma unroll
    for (int t = 0; t < 4; t++) {
        uint32_t hi[4], lo[4];
#pragma unroll
        for (int q = 0; q < 2; q++) {
            const int nt = 2*t + q;
            const int n0 = c0 + 8*nt + nb;
            const float b0 = bias[n0], b1 = bias[n0+1];
            float v00 = ok0 ? fmaxf(acc[nt][0] + b0, 0.f) : 0.f;
            float v01 = ok0 ? fmaxf(acc[nt][1] + b1, 0.f) : 0.f;
            float v10 = ok1 ? fmaxf(acc[nt][2] + b0, 0.f) : 0.f;
            float v11 = ok1 ? fmaxf(acc[nt][3] + b1, 0.f) : 0.f;
            float h0, l0, h1, l1;
            splitf(v00, h0, l0); splitf(v01, h1, l1);
            hi[2*q]   = pkbf(h0, h1); lo[2*q]   = pkbf(l0, l1);
            splitf(v10, h0, l0); splitf(v11, h1, l1);
            hi[2*q+1] = pkbf(h0, h1); lo[2*q+1] = pkbf(l0, l1);
        }
        stsm4(aHu + t*32, hi[0], hi[1], hi[2], hi[3]);
        stsm4(aLu + t*32, lo[0], lo[1], lo[2], lo[3]);
    }
}

// Stage W^T into Bt[n][k] hi/lo, processing k-PAIRS (one STS.32 per buf).
__device__ __forceinline__ void stageW(const float* __restrict__ W, int K,
                                       char* bH, char* bL, int tid)
{
    const int tot = (K/2)*128;
    for (int idx = tid; idx < tot; idx += 512) {
        const int kp = idx >> 7, n = idx & 127;
        const float v0 = W[(size_t)(2*kp)*128 + n];
        const float v1 = W[(size_t)(2*kp+1)*128 + n];
        float h0, l0, h1, l1;
        splitf(v0, h0, l0); splitf(v1, h1, l1);
        const uint32_t o = (uint32_t)n*SA + kp*4;
        *reinterpret_cast<uint32_t*>(bH + o) = pkbf(h0, h1);
        *reinterpret_cast<uint32_t*>(bL + o) = pkbf(l0, l1);
    }
}

// ---------------------------------------------------------------------------
__global__ void __launch_bounds__(512, 1) gcn_kernel(
    const float* __restrict__ x,
    const float* __restrict__ W1, const float* __restrict__ b1,
    const float* __restrict__ W2, const float* __restrict__ b2,
    const float* __restrict__ W3, const float* __restrict__ b3)
{
    extern __shared__ char smd[];
    char* sAh = smd;
    char* sAl = smd + 30464;
    char* sBh = smd + 60928;
    char* sBl = smd + 95744;
    char* sJh = smd + 130560;
    char* sJl = smd + 157440;

    __shared__ float xc[128][WIN];
    __shared__ float invd[128], dinv[128];

    const int g    = blockIdx.x;
    const int tid  = threadIdx.x;
    const int warp = tid >> 5;
    const int lane = tid & 31;
    const int wm   = warp >> 1;        // M-tile 0..7 (7 used)
    const int nh   = warp & 1;         // N-half 0/1
    const int m0   = wm * 16;
    const int c0   = nh * 64;
    const bool act = (wm < 7);         // 14 compute warps

    if (tid < AA) {
        float r[WIN]; float s = 0.f;
#pragma unroll
        for (int t = 0; t < WIN; t++) {
            r[t] = x[((size_t)(g*AA + tid)*WIN + t)*FDIM + (FDIM-1)]; s += r[t];
        }
        const float mean = s * (1.0f/WIN); float ss = 0.f;
#pragma unroll
        for (int t = 0; t < WIN; t++) { float v = r[t]-mean; xc[tid][t] = v; ss += v*v; }
        invd[tid] = rsqrtf(ss);
    } else if (tid < 128) {
        invd[tid] = 0.f;
#pragma unroll
        for (int t = 0; t < WIN; t++) xc[tid][t] = 0.f;
    }
    __syncthreads();

    // dinv: 4 threads per row (quad-split j), shuffle-quad reduce.
    {
        const int i = tid >> 2, q = tid & 3;
        float xi[WIN];
#pragma unroll
        for (int t = 0; t < WIN; t++) xi[t] = xc[i][t];
        const float di = invd[i];
        float rs = 0.f;
        const int j0 = q*25;
#pragma unroll 5
        for (int j = j0; j < j0 + 25; j++) {
            float dot = 0.f;
#pragma unroll
            for (int t = 0; t < WIN; t++) dot = fmaf(xi[t], xc[j][t], dot);
            rs += 1.0f - fabsf(dot * di * invd[j]);
        }
        rs += __shfl_xor_sync(0xffffffffu, rs, 1);
        rs += __shfl_xor_sync(0xffffffffu, rs, 2);
        if (q == 0 && i < AA) dinv[i] = rsqrtf(rs + 1.0f);
    }
    __syncthreads();

    // Adjacency staging: j-pairs, one STS.32 per buffer per pair.
    for (int e = tid; e < MM*(MM/2); e += 512) {
        const int i = e / (MM/2), jp = e - i*(MM/2);
        const int j0 = 2*jp, j1 = j0 + 1;
        float a0 = 0.f, a1 = 0.f;
        if (i < AA) {
            float xi[WIN];
#pragma unroll
            for (int t = 0; t < WIN; t++) xi[t] = xc[i][t];
            if (j0 < AA) {
                float dot = 0.f;
#pragma unroll
                for (int t = 0; t < WIN; t++) dot = fmaf(xi[t], xc[j0][t], dot);
                float c = dot * invd[i] * invd[j0];
                a0 = (1.0f - fabsf(c) + (i == j0 ? 1.0f : 0.0f)) * dinv[i] * dinv[j0];
            }
            if (j1 < AA) {
                float dot = 0.f;
#pragma unroll
                for (int t = 0; t < WIN; t++) dot = fmaf(xi[t], xc[j1][t], dot);
                float c = dot * invd[i] * invd[j1];
                a1 = (1.0f - fabsf(c) + (i == j1 ? 1.0f : 0.0f)) * dinv[i] * dinv[j1];
            }
        }
        float h0, l0, h1, l1;
        splitf(a0, h0, l0); splitf(a1, h1, l1);
        const uint32_t o = (uint32_t)i*SJ + j0*2;
        *reinterpret_cast<uint32_t*>(sJh + o) = pkbf(h0, h1);
        *reinterpret_cast<uint32_t*>(sJl + o) = pkbf(l0, l1);
    }

    float acc[8][4];
    zero_acc(acc);

#pragma unroll 1
    for (int c = 0; c < 2; c++) {
        __syncthreads();
        // x staging: k-pairs via float2 loads, one STS.32 per buffer.
        for (int idx = tid; idx < MM*40; idx += 512) {
            const int r = idx / 40, kp = idx - r*40;
            float2 v = make_float2(0.f, 0.f);
            if (r < AA)
                v = *reinterpret_cast<const float2*>(
                        x + ((size_t)(g*AA + r))*K1 + 80*c + 2*kp);
            float h0, l0, h1, l1;
            splitf(v.x, h0, l0); splitf(v.y, h1, l1);
            const uint32_t o = (uint32_t)r*SA + kp*4;
            *reinterpret_cast<uint32_t*>(sAh + o) = pkbf(h0, h1);
            *reinterpret_cast<uint32_t*>(sAl + o) = pkbf(l0, l1);
        }
        stageW(W1 + (size_t)80*c*128, 80, sBh, sBl, tid);
        __syncthreads();
        if (act) gemm_mma<5, SA>(sAh, sAl, sBh, sBl, acc, lane, m0, nh);
    }
    __syncthreads();
    if (act) epi_T(acc, sBh, sBl, lane, m0, c0);
    __syncthreads();

    zero_acc(acc);
    if (act) gemm_mma<7, SJ>(sJh, sJl, sBh, sBl, acc, lane, m0, nh);
    __syncthreads();
    if (act) epi_A<false>(acc, b1, sAh, sAl, nullptr, lane, m0, c0);
    stageW(W2, HD, sBh, sBl, tid);
    __syncthreads();

    zero_acc(acc);
    if (act) gemm_mma<8, SA>(sAh, sAl, sBh, sBl, acc, lane, m0, nh);
    __syncthreads();
    if (act) epi_T(acc, sBh, sBl, lane, m0, c0);
    __syncthreads();

    zero_acc(acc);
    if (act) gemm_mma<7, SJ>(sJh, sJl, sBh, sBl, acc, lane, m0, nh);
    __syncthreads();
    if (act) epi_A<false>(acc, b2, sAh, sAl, nullptr, lane, m0, c0);
    stageW(W3, HD, sBh, sBl, tid);
    __syncthreads();

    zero_acc(acc);
    if (act) gemm_mma<8, SA>(sAh, sAl, sBh, sBl, acc, lane, m0, nh);
    __syncthreads();
    if (act) epi_T(acc, sBh, sBl, lane, m0, c0);
    __syncthreads();

    zero_acc(acc);
    if (act) gemm_mma<7, SJ>(sJh, sJl, sBh, sBl, acc, lane, m0, nh);
    if (act) epi_A<true>(acc, b3, nullptr, nullptr, g_h + (size_t)g*AA*HD, lane, m0, c0);
}

// ---------------------------------------------------------------------------
// conv1(relu)+conv2 fused, 1 row/warp. Weights from __constant__ (uniform
// LDCU -> UR operands; FFMA2 drops to 2 distinct GPR banks).
// ---------------------------------------------------------------------------
__global__ void __launch_bounds__(256) conv_kernel(float* __restrict__ out,
                                                   const float* __restrict__ cb2)
{
    const int tid  = threadIdx.x;
    const int warp = tid >> 5, lane = tid & 31;
    const int row  = blockIdx.x*8 + warp;

    const float4 hv = reinterpret_cast<const float4*>(g_h + (size_t)row*HD)[lane];
    float hm1 = __shfl_up_sync(0xffffffffu, hv.w, 1);  if (lane == 0)  hm1 = 0.f;
    float hp1 = __shfl_down_sync(0xffffffffu, hv.x, 1); if (lane == 31) hp1 = 0.f;

    const ull Pm = pk2(hm1,  hv.x);
    const ull P0 = pk2(hv.x, hv.y);
    const ull P1 = pk2(hv.y, hv.z);
    const ull P2 = pk2(hv.z, hv.w);
    const ull P3 = pk2(hv.w, hp1);
    const ull M = 0x7FFFFFFF7FFFFFFFull;

    ull T0a=0, T0b=0, T1a=0, T1b=0, T2a=0, T2b=0;
#pragma unroll 8
    for (int c = 0; c < HD; c++) {
        const ull q0x = c_wpk[c*8+0];
        const ull q0y = c_wpk[c*8+1];
        const ull q1x = c_wpk[c*8+2];
        const ull q1y = c_wpk[c*8+3];
        const ull q2x = c_wpk[c*8+4];
        const ull q2y = c_wpk[c*8+5];
        const ull q3  = c_wpk[c*8+6];
        ull z01 = fma2(q0x, Pm, fma2(q0y, P0, fma2(q1x, P1, q1y)));
        ull z23 = fma2(q0x, P1, fma2(q0y, P2, fma2(q1x, P3, q1y)));
        z01 = add2(z01, z01 & M);   // 2*relu(z); 0.5 folded into u-weights
        z23 = add2(z23, z23 & M);
        T0a = fma2(q2x, z01, T0a);  T0b = fma2(q2x, z23, T0b);
        T1a = fma2(q2y, z01, T1a);  T1b = fma2(q2y, z23, T1b);
        T2a = fma2(q3,  z01, T2a);  T2b = fma2(q3,  z23, T2b);
    }
    const float2 t0a = upk2(T0a), t0b = upk2(T0b);
    const float2 t1a = upk2(T1a), t1b = upk2(T1b);
    const float2 t2a = upk2(T2a), t2b = upk2(T2b);

    float t0m = __shfl_up_sync(0xffffffffu, t0b.y, 1);  if (lane == 0)  t0m = 0.f;
    float t2p = __shfl_down_sync(0xffffffffu, t2a.x, 1); if (lane == 31) t2p = 0.f;

    const float c2 = cb2[0];
    float4 res;
    res.x = t0m   + t1a.x + t2a.y + c2;
    res.y = t0a.x + t1a.y + t2b.x + c2;
    res.z = t0a.y + t1b.x + t2b.y + c2;
    res.w = t0b.x + t1b.y + t2p   + c2;
    reinterpret_cast<float4*>(out + (size_t)row*HD)[lane] = res;
}

// ---------------------------------------------------------------------------
extern "C" void kernel_launch(void* const* d_in, const int* in_sizes, int n_in,
                              void* d_out, int out_size)
{
    const float* x   = (const float*)d_in[0];
    const float* W1  = (const float*)d_in[1];
    const float* b1  = (const float*)d_in[2];
    const float* W2  = (const float*)d_in[3];
    const float* b2  = (const float*)d_in[4];
    const float* W3  = (const float*)d_in[5];
    const float* b3  = (const float*)d_in[6];
    const float* cw1 = (const float*)d_in[7];
    const float* cb1 = (const float*)d_in[8];
    const float* cw2 = (const float*)d_in[9];
    const float* cb2 = (const float*)d_in[10];
    float* out = (float*)d_out;

    const int SMEM = 184320;
    cudaFuncSetAttribute(gcn_kernel, cudaFuncAttributeMaxDynamicSharedMemorySize, SMEM);

    // Pack conv weights -> gmem staging -> constant bank (async D2D, capturable)
    packW_kernel<<<1, 128>>>(cw1, cb1, cw2);
    void* wtmp_ptr = nullptr;
    cudaGetSymbolAddress(&wtmp_ptr, g_wtmp);
    cudaMemcpyToSymbolAsync(c_wpk, wtmp_ptr, HD*8*sizeof(ull), 0,
                            cudaMemcpyDeviceToDevice, 0);

    gcn_kernel<<<GG, 512, SMEM>>>(x, W1, b1, W2, b2, W3, b3);
    conv_kernel<<<NN/8, 256>>>(out, cb2);
}